// round 2
// baseline (speedup 1.0000x reference)
#include <cuda_runtime.h>
#include <cstdint>

// DepthEmissionRaymarcher: B=2,H=192,W=320,P=128,F=8
// One warp per ray. Warp-scan cumsum of densities (wall=1 on last point),
// clamp to 1, diff -> absorption probs. depth = sum(probs*len),
// features = sum(probs * feat).
// Streaming HBM-bound: ~629 MB read, ~4.4 MB write.

static constexpr int P = 128;
static constexpr int F = 8;
static constexpr int WARPS_PER_BLOCK = 8;
static constexpr int THREADS = WARPS_PER_BLOCK * 32;

__global__ __launch_bounds__(THREADS, 8)
void raymarch_kernel(const float* __restrict__ dens,
                     const float* __restrict__ feat,
                     const float* __restrict__ len,
                     float* __restrict__ depth_out,
                     float* __restrict__ feat_out,
                     int R)
{
    __shared__ float sprobs[WARPS_PER_BLOCK][P];

    const int lane = threadIdx.x & 31;
    const int warp_in_block = threadIdx.x >> 5;
    const int ray = blockIdx.x * WARPS_PER_BLOCK + warp_in_block;
    if (ray >= R) return;  // whole warp exits together

    // ---- densities: coalesced float4, points 4*lane .. 4*lane+3 ----
    const float4 d4 = reinterpret_cast<const float4*>(dens + (size_t)ray * P)[lane];
    float d0 = d4.x, d1 = d4.y, d2 = d4.z, d3 = d4.w;
    if (lane == 31) d3 = 1.0f;  // wall=True: furthest sample density = 1

    // lane-local inclusive prefix
    const float s0 = d0;
    const float s1 = s0 + d1;
    const float s2 = s1 + d2;
    const float s3 = s2 + d3;

    // warp inclusive scan of lane totals -> exclusive prefix for this lane
    float incl = s3;
    #pragma unroll
    for (int off = 1; off < 32; off <<= 1) {
        float v = __shfl_up_sync(0xffffffffu, incl, off);
        if (lane >= off) incl += v;
    }
    const float excl = incl - s3;

    // cumulative sums clamped to 1, then diff -> probs
    const float cprev = fminf(excl, 1.0f);
    const float c0 = fminf(excl + s0, 1.0f);
    const float c1 = fminf(excl + s1, 1.0f);
    const float c2 = fminf(excl + s2, 1.0f);
    const float c3 = fminf(excl + s3, 1.0f);
    const float p0 = c0 - cprev;
    const float p1 = c1 - c0;
    const float p2 = c2 - c1;
    const float p3 = c3 - c2;

    // ---- depth: probs . lengths ----
    const float4 l4 = reinterpret_cast<const float4*>(len + (size_t)ray * P)[lane];
    float dpart = p0 * l4.x + p1 * l4.y + p2 * l4.z + p3 * l4.w;
    #pragma unroll
    for (int off = 16; off > 0; off >>= 1)
        dpart += __shfl_xor_sync(0xffffffffu, dpart, off);
    if (lane == 0) depth_out[ray] = dpart;

    // ---- stash probs to shared for feature pass ----
    sprobs[warp_in_block][lane * 4 + 0] = p0;
    sprobs[warp_in_block][lane * 4 + 1] = p1;
    sprobs[warp_in_block][lane * 4 + 2] = p2;
    sprobs[warp_in_block][lane * 4 + 3] = p3;
    __syncwarp();

    // ---- features: (P,F)=128x8 floats = 256 float4 per ray.
    // float4 index k = lane + 32*j : point = k>>1, feature-half = k&1.
    // Parity of k == parity of lane, so even lanes accumulate feats[0:4],
    // odd lanes feats[4:8].
    const float4* fv = reinterpret_cast<const float4*>(feat + (size_t)ray * P * F);
    float a0 = 0.f, a1 = 0.f, a2 = 0.f, a3 = 0.f;
    #pragma unroll
    for (int j = 0; j < 8; j++) {
        const int k = lane + 32 * j;
        const float4 f = fv[k];
        const float pw = sprobs[warp_in_block][k >> 1];
        a0 += pw * f.x;
        a1 += pw * f.y;
        a2 += pw * f.z;
        a3 += pw * f.w;
    }
    // reduce within parity class (xor offsets 2..16 preserve lane parity)
    #pragma unroll
    for (int off = 16; off >= 2; off >>= 1) {
        a0 += __shfl_xor_sync(0xffffffffu, a0, off);
        a1 += __shfl_xor_sync(0xffffffffu, a1, off);
        a2 += __shfl_xor_sync(0xffffffffu, a2, off);
        a3 += __shfl_xor_sync(0xffffffffu, a3, off);
    }
    // lane 0 holds feats[0:4] sum, lane 1 holds feats[4:8] sum
    if (lane < 2) {
        float4 outv = make_float4(a0, a1, a2, a3);
        reinterpret_cast<float4*>(feat_out + (size_t)ray * F)[lane] = outv;
    }
}

extern "C" void kernel_launch(void* const* d_in, const int* in_sizes, int n_in,
                              void* d_out, int out_size)
{
    const float* dens = (const float*)d_in[0];  // (B,H,W,P,1)
    const float* feat = (const float*)d_in[1];  // (B,H,W,P,F)
    const float* len  = (const float*)d_in[2];  // (B,H,W,P)

    const int R = in_sizes[2] / P;              // number of rays

    float* depth_out = (float*)d_out;           // (B,H,W) flattened
    float* feat_out  = depth_out + R;           // (B,H,W,F) flattened

    const int blocks = (R + WARPS_PER_BLOCK - 1) / WARPS_PER_BLOCK;
    raymarch_kernel<<<blocks, THREADS>>>(dens, feat, len, depth_out, feat_out, R);
}

// round 3
// speedup vs baseline: 1.0035x; 1.0035x over previous
#include <cuda_runtime.h>
#include <cstdint>

// DepthEmissionRaymarcher: B=2,H=192,W=320,P=128,F=8
// One warp per ray. Warp-scan cumsum of densities (wall=1 on last point),
// clamp to 1, diff -> absorption probs. depth = sum(probs*len),
// features = sum(probs * feat).
// HBM-bound (~629 MB read). R2: front-batch all 10 LDG.128/lane (MLP=10)
// with __ldcs streaming hints; let ptxas use ~72 regs.

static constexpr int P = 128;
static constexpr int F = 8;
static constexpr int WARPS_PER_BLOCK = 8;
static constexpr int THREADS = WARPS_PER_BLOCK * 32;

__global__ __launch_bounds__(THREADS)
void raymarch_kernel(const float* __restrict__ dens,
                     const float* __restrict__ feat,
                     const float* __restrict__ len,
                     float* __restrict__ depth_out,
                     float* __restrict__ feat_out,
                     int R)
{
    __shared__ float sprobs[WARPS_PER_BLOCK][P];

    const int lane = threadIdx.x & 31;
    const int warp_in_block = threadIdx.x >> 5;
    const int ray = blockIdx.x * WARPS_PER_BLOCK + warp_in_block;
    if (ray >= R) return;  // whole warp exits together

    // ---- front-batched loads: 10 independent LDG.128 per lane ----
    const float4 d4 = __ldcs(reinterpret_cast<const float4*>(dens + (size_t)ray * P) + lane);
    const float4 l4 = __ldcs(reinterpret_cast<const float4*>(len  + (size_t)ray * P) + lane);
    const float4* fv = reinterpret_cast<const float4*>(feat + (size_t)ray * P * F);
    float4 f[8];
    #pragma unroll
    for (int j = 0; j < 8; j++)
        f[j] = __ldcs(fv + lane + 32 * j);

    // ---- density scan (wall=1 on last point) ----
    float d0 = d4.x, d1 = d4.y, d2 = d4.z, d3 = d4.w;
    if (lane == 31) d3 = 1.0f;

    const float s0 = d0;
    const float s1 = s0 + d1;
    const float s2 = s1 + d2;
    const float s3 = s2 + d3;

    float incl = s3;
    #pragma unroll
    for (int off = 1; off < 32; off <<= 1) {
        float v = __shfl_up_sync(0xffffffffu, incl, off);
        if (lane >= off) incl += v;
    }
    const float excl = incl - s3;

    const float cprev = fminf(excl, 1.0f);
    const float c0 = fminf(excl + s0, 1.0f);
    const float c1 = fminf(excl + s1, 1.0f);
    const float c2 = fminf(excl + s2, 1.0f);
    const float c3 = fminf(excl + s3, 1.0f);
    const float p0 = c0 - cprev;
    const float p1 = c1 - c0;
    const float p2 = c2 - c1;
    const float p3 = c3 - c2;

    // ---- depth: probs . lengths ----
    float dpart = p0 * l4.x + p1 * l4.y + p2 * l4.z + p3 * l4.w;
    #pragma unroll
    for (int off = 16; off > 0; off >>= 1)
        dpart += __shfl_xor_sync(0xffffffffu, dpart, off);
    if (lane == 0) depth_out[ray] = dpart;

    // ---- stash probs to shared for feature weighting ----
    sprobs[warp_in_block][lane * 4 + 0] = p0;
    sprobs[warp_in_block][lane * 4 + 1] = p1;
    sprobs[warp_in_block][lane * 4 + 2] = p2;
    sprobs[warp_in_block][lane * 4 + 3] = p3;
    __syncwarp();

    // ---- features: float4 index k = lane + 32*j -> point k>>1, half k&1.
    // Parity of k == parity of lane: even lanes accumulate feats[0:4],
    // odd lanes feats[4:8].
    float a0 = 0.f, a1 = 0.f, a2 = 0.f, a3 = 0.f;
    #pragma unroll
    for (int j = 0; j < 8; j++) {
        const int k = lane + 32 * j;
        const float pw = sprobs[warp_in_block][k >> 1];
        a0 += pw * f[j].x;
        a1 += pw * f[j].y;
        a2 += pw * f[j].z;
        a3 += pw * f[j].w;
    }
    #pragma unroll
    for (int off = 16; off >= 2; off >>= 1) {
        a0 += __shfl_xor_sync(0xffffffffu, a0, off);
        a1 += __shfl_xor_sync(0xffffffffu, a1, off);
        a2 += __shfl_xor_sync(0xffffffffu, a2, off);
        a3 += __shfl_xor_sync(0xffffffffu, a3, off);
    }
    if (lane < 2) {
        float4 outv = make_float4(a0, a1, a2, a3);
        reinterpret_cast<float4*>(feat_out + (size_t)ray * F)[lane] = outv;
    }
}

extern "C" void kernel_launch(void* const* d_in, const int* in_sizes, int n_in,
                              void* d_out, int out_size)
{
    const float* dens = (const float*)d_in[0];  // (B,H,W,P,1)
    const float* feat = (const float*)d_in[1];  // (B,H,W,P,F)
    const float* len  = (const float*)d_in[2];  // (B,H,W,P)

    const int R = in_sizes[2] / P;              // number of rays

    float* depth_out = (float*)d_out;           // (B,H,W) flattened
    float* feat_out  = depth_out + R;           // (B,H,W,F) flattened

    const int blocks = (R + WARPS_PER_BLOCK - 1) / WARPS_PER_BLOCK;
    raymarch_kernel<<<blocks, THREADS>>>(dens, feat, len, depth_out, feat_out, R);
}